// round 11
// baseline (speedup 1.0000x reference)
#include <cuda_runtime.h>

// Problem constants (fixed by reference_code)
#define Bc 2
#define Nc 65536
#define Hc 128
#define Wc 128
#define HWc 16384
#define NTX 8
#define NTY 8
#define TDIMX 16
#define TDIMY 16
#define NTILE 64               // tiles per camera
#define NBT (Bc * NTILE)       // 128 (camera, tile) pairs
#define NCHUNK 256             // 256-gaussian chunks per camera
#define SEG 256                // list entries per splat work item
#define KC 32                  // staged chunk in splat
#define NTHR 128
// cutoff: op*exp(a*d^2) <= e^-14 ~ 8.3e-7; validated rel_err ~9.3e-7 (R7-R9)
#define CULL_LN (-14.0f)
#define LISTCAP (Bc * Nc * 9 + 64)   // every gaussian covers <= 9 tiles (r < 16)
#define MAXITEMS 4800                // >= LISTCAP/SEG + NBT

// Scratch (static __device__ arrays — no allocation at runtime)
__device__ float4 g_params[Bc * Nc];            // proj_x, proj_y, a=-0.5/var, opacity
__device__ float4 g_colop[Nc];                  // (op*cr, op*cg, op*cb, op)
__device__ unsigned long long g_mask[Bc * Nc];  // 64-bit tile cover mask
__device__ unsigned int g_cnt[NBT * NCHUNK];    // per (b,tile,chunk) counts
__device__ unsigned int g_off[NBT * NCHUNK];    // exclusive prefix within (b,tile)
__device__ int g_tilebase[NBT + 1];             // list base per (b,tile)
__device__ int g_itembase[NBT + 1];             // item base per (b,tile)
__device__ int g_nitems;
__device__ unsigned int g_items[MAXITEMS];      // b<<24 | tile<<16 | seg
__device__ unsigned short g_list[LISTCAP];      // gaussian index within camera
__device__ float g_part[(size_t)MAXITEMS * 1024]; // per-item partials [4ch][256px]

// ---------------------------------------------------------------------------
// Kernel 0: fold opacity into colors (camera-independent)
// ---------------------------------------------------------------------------
__global__ void k_colop(const float* __restrict__ colors,
                        const float* __restrict__ opa) {
    int n = blockIdx.x * blockDim.x + threadIdx.x;
    if (n >= Nc) return;
    float op = opa[n];
    g_colop[n] = make_float4(op * colors[3 * n], op * colors[3 * n + 1],
                             op * colors[3 * n + 2], op);
}

// ---------------------------------------------------------------------------
// Kernel 1: projection params + tile-cover mask + per-chunk tile counts.
//   grid = 512 blocks (b = blk>>8, chunk c = blk&255), 256 threads.
// ---------------------------------------------------------------------------
__global__ void __launch_bounds__(256) k_params(
        const float* __restrict__ pos,
        const float* __restrict__ opa,
        const float* __restrict__ scl,
        const float* __restrict__ qv,
        const float* __restrict__ tv,
        const float* __restrict__ fx_,
        const float* __restrict__ fy_,
        const float* __restrict__ cx_,
        const float* __restrict__ cy_) {
    __shared__ unsigned int scnt[NTILE];

    const int t = threadIdx.x;
    const int b = blockIdx.x >> 8;
    const int c = blockIdx.x & 255;
    const int n = c * 256 + t;
    const int idx = b * Nc + n;

    if (t < NTILE) scnt[t] = 0u;
    __syncthreads();

    float qw = qv[b * 4 + 0], qx = qv[b * 4 + 1], qy = qv[b * 4 + 2], qz = qv[b * 4 + 3];
    float inv = rsqrtf(qw * qw + qx * qx + qy * qy + qz * qz);
    qw *= inv; qx *= inv; qy *= inv; qz *= inv;

    float R00 = 1.f - 2.f * (qy * qy + qz * qz);
    float R01 = 2.f * (qx * qy - qz * qw);
    float R02 = 2.f * (qx * qz + qy * qw);
    float R10 = 2.f * (qx * qy + qz * qw);
    float R11 = 1.f - 2.f * (qx * qx + qz * qz);
    float R12 = 2.f * (qy * qz - qx * qw);
    float R20 = 2.f * (qx * qz - qy * qw);
    float R21 = 2.f * (qy * qz + qx * qw);
    float R22 = 1.f - 2.f * (qx * qx + qy * qy);

    float px = pos[3 * n], py = pos[3 * n + 1], pz = pos[3 * n + 2];
    float cxm = R00 * px + R01 * py + R02 * pz + tv[b * 3 + 0];
    float cym = R10 * px + R11 * py + R12 * pz + tv[b * 3 + 1];
    float czm = R20 * px + R21 * py + R22 * pz + tv[b * 3 + 2];

    float projx = cxm / czm * fx_[0] + cx_[0];
    float projy = cym / czm * fy_[0] + cy_[0];
    float s = scl[n];
    float a = -0.5f / (s * s);

    g_params[idx] = make_float4(projx, projy, a, opa[n]);

    // tile cover mask (exact clamped-corner test, NaN-safe: NaN>=c is false)
    unsigned long long mask = 0ull;
    float r2lim = CULL_LN / a;                 // = 28*var > 0
    float r = sqrtf(r2lim);
    int txlo = (int)fmaxf(0.f, fminf(7.f, floorf((projx - r) * 0.0625f)));
    int txhi = (int)fmaxf(0.f, fminf(7.f, floorf((projx + r) * 0.0625f)));
    int tylo = (int)fmaxf(0.f, fminf(7.f, floorf((projy - r) * 0.0625f)));
    int tyhi = (int)fmaxf(0.f, fminf(7.f, floorf((projy + r) * 0.0625f)));
    for (int ty = tylo; ty <= tyhi; ty++) {
        float ylo = (float)(ty * 16), yhi = ylo + 15.f;
        float ey = fmaxf(fmaxf(ylo - projy, projy - yhi), 0.f);
        for (int tx = txlo; tx <= txhi; tx++) {
            float xlo = (float)(tx * 16), xhi = xlo + 15.f;
            float ex = fmaxf(fmaxf(xlo - projx, projx - xhi), 0.f);
            if (a * (ex * ex + ey * ey) >= CULL_LN)
                mask |= 1ull << (ty * 8 + tx);
        }
    }
    g_mask[idx] = mask;

    // per-tile counts via ballots
    const int lane = t & 31;
    for (int tl = 0; tl < NTILE; tl++) {
        unsigned bal = __ballot_sync(0xffffffffu, (mask >> tl) & 1ull);
        if (lane == 0 && bal) atomicAdd(&scnt[tl], (unsigned)__popc(bal));
    }
    __syncthreads();
    if (t < NTILE) g_cnt[(b * NTILE + t) * NCHUNK + c] = scnt[t];
}

// ---------------------------------------------------------------------------
// Kernel 2: scan — per-(b,tile) chunk prefix, tile bases, item table.
//   Single block, 256 threads.
// ---------------------------------------------------------------------------
__global__ void __launch_bounds__(256) k_scan() {
    __shared__ int slen[NBT];
    __shared__ int stb[NBT + 1];
    __shared__ int sib[NBT + 1];
    const int t = threadIdx.x;

    if (t < NBT) {
        unsigned run = 0;
        const int base = t * NCHUNK;
        for (int c = 0; c < NCHUNK; c++) {
            unsigned v = g_cnt[base + c];
            g_off[base + c] = run;
            run += v;
        }
        slen[t] = (int)run;
    }
    __syncthreads();
    if (t == 0) {
        int tb = 0, ib = 0;
        for (int i = 0; i < NBT; i++) {
            stb[i] = tb; sib[i] = ib;
            tb += slen[i];
            ib += (slen[i] + SEG - 1) / SEG;
        }
        stb[NBT] = tb; sib[NBT] = ib;
        g_nitems = ib;
    }
    __syncthreads();
    if (t <= NBT) { g_tilebase[t] = stb[t]; g_itembase[t] = sib[t]; }
    if (t < NBT) {
        int ns = (slen[t] + SEG - 1) / SEG;
        unsigned hdr = ((unsigned)(t >> 6) << 24) | ((unsigned)(t & 63) << 16);
        for (int s = 0; s < ns; s++)
            g_items[sib[t] + s] = hdr | (unsigned)s;
    }
}

// ---------------------------------------------------------------------------
// Kernel 3: scatter gaussian indices into per-tile lists (index-ordered).
//   grid = 512 blocks (b, chunk), 256 threads.
// ---------------------------------------------------------------------------
__global__ void __launch_bounds__(256) k_scatter() {
    __shared__ unsigned int bals[8][NTILE];

    const int t = threadIdx.x;
    const int b = blockIdx.x >> 8;
    const int c = blockIdx.x & 255;
    const int n = c * 256 + t;
    const unsigned long long mask = g_mask[b * Nc + n];
    const int wid = t >> 5, lane = t & 31;

    for (int tl = 0; tl < NTILE; tl++) {
        unsigned bal = __ballot_sync(0xffffffffu, (mask >> tl) & 1ull);
        if (lane == 0) bals[wid][tl] = bal;
    }
    __syncthreads();

    unsigned long long mm = mask;
    while (mm) {
        int tl = __ffsll((long long)mm) - 1;
        mm &= mm - 1;
        int rank = 0;
#pragma unroll
        for (int w = 0; w < 8; w++) {
            unsigned bb = bals[w][tl];
            if (w < wid) rank += __popc(bb);
            else if (w == wid) rank += __popc(bb & ((1u << lane) - 1u));
        }
        int bt = b * NTILE + tl;
        int pos = g_tilebase[bt] + (int)g_off[bt * NCHUNK + c] + rank;
        g_list[pos] = (unsigned short)n;
    }
}

// ---------------------------------------------------------------------------
// Kernel 4: splat — one 256-entry list segment per block (perfect balance).
//   grid = MAXITEMS blocks (early exit past g_nitems), 128 threads.
//   Inner: LDS.64 + LDS.128 + 8 FFMA per gaussian per thread (R9-proven).
// ---------------------------------------------------------------------------
__global__ void __launch_bounds__(NTHR) k_splat() {
    __shared__ float  us[KC][TDIMX];
    __shared__ float4 ds[KC][TDIMY];
    __shared__ unsigned short lst[SEG];

    const int item = blockIdx.x;
    if (item >= g_nitems) return;
    const unsigned rec = g_items[item];
    const int b = rec >> 24, tile = (rec >> 16) & 0xff, seg = rec & 0xffff;
    const int bt = b * NTILE + tile;
    const int base = g_tilebase[bt];
    const int len = g_tilebase[bt + 1] - base;
    const int start = seg * SEG;
    const int m = min(SEG, len - start);
    const int t = threadIdx.x;

    // preload list slice (2 scalar u16 loads / thread — base may be odd)
    if (t < m)           lst[t] = g_list[base + start + t];
    if (t + NTHR < m)    lst[t + NTHR] = g_list[base + start + t + NTHR];

    const float4* __restrict__ prm = &g_params[b * Nc];
    const int x0 = (tile & 7) * TDIMX, y0 = (tile >> 3) * TDIMY;
    const int tx = t & 7, tyy = t >> 3;     // 2x * 1y micro-tile
    const int xu = t & 15, ku0 = t >> 4;    // staging: 4 slots (k = ku0 + 8i)

    float acc[2][4];
#pragma unroll
    for (int xi = 0; xi < 2; xi++)
#pragma unroll
        for (int ch = 0; ch < 4; ch++) acc[xi][ch] = 0.f;

    __syncthreads();

    for (int kb = 0; kb < m; kb += KC) {
        // ---- stage u
#pragma unroll
        for (int i = 0; i < 4; i++) {
            int k = ku0 + i * 8;
            int kk = kb + k;
            float u = 0.f;
            if (kk < m) {
                int n = (int)lst[kk];
                float4 pr = prm[n];
                float dx = (float)(x0 + xu) - pr.x;
                u = __expf(pr.z * dx * dx);
            }
            us[k][xu] = u;
        }
        // ---- stage d (folded colors, one exp)
#pragma unroll
        for (int i = 0; i < 4; i++) {
            int k = ku0 + i * 8;
            int kk = kb + k;
            float4 dval = make_float4(0.f, 0.f, 0.f, 0.f);
            if (kk < m) {
                int n = (int)lst[kk];
                float4 pr = prm[n];
                float4 co = g_colop[n];
                float dy = (float)(y0 + xu) - pr.y;
                float e  = __expf(pr.z * dy * dy);
                dval = make_float4(co.x * e, co.y * e, co.z * e, co.w * e);
            }
            ds[k][xu] = dval;
        }
        __syncthreads();

        // ---- inner: 8 FFMA + LDS.64 + LDS.128 per k
#pragma unroll 16
        for (int k = 0; k < KC; k++) {
            float2 u2 = *reinterpret_cast<const float2*>(&us[k][tx * 2]);
            float4 d  = ds[k][tyy];
            acc[0][0] += u2.x * d.x;
            acc[0][1] += u2.x * d.y;
            acc[0][2] += u2.x * d.z;
            acc[0][3] += u2.x * d.w;
            acc[1][0] += u2.y * d.x;
            acc[1][1] += u2.y * d.y;
            acc[1][2] += u2.y * d.z;
            acc[1][3] += u2.y * d.w;
        }
        __syncthreads();
    }

    // ---- write per-item partial [4ch][256px]
    float* pb = &g_part[(size_t)item * 1024];
    const int p = tyy * 16 + tx * 2;
#pragma unroll
    for (int ch = 0; ch < 4; ch++)
        *reinterpret_cast<float2*>(&pb[ch * 256 + p]) =
            make_float2(acc[0][ch], acc[1][ch]);
}

// ---------------------------------------------------------------------------
// Kernel 5: finalize — per-(b,tile) block sums its segments, divides, writes.
// ---------------------------------------------------------------------------
__global__ void __launch_bounds__(256) k_finalize(float* __restrict__ out) {
    const int bt = blockIdx.x;
    const int b = bt >> 6, tile = bt & 63;
    const int t = threadIdx.x;
    const int itb = g_itembase[bt];
    const int ns = g_itembase[bt + 1] - itb;

    float r = 0.f, gg = 0.f, bb = 0.f;
    float d = 32.0f * 1e-8f;   // n_chunks(=32 of 2048) * EPS from reference scan
    for (int s = 0; s < ns; s++) {
        const float* pb = &g_part[(size_t)(itb + s) * 1024];
        r  += pb[t];
        gg += pb[256 + t];
        bb += pb[512 + t];
        d  += pb[768 + t];
    }
    float inv = 1.0f / fmaxf(d, 1e-8f);
    const int col = t & 15, row = t >> 4;
    const int p = ((tile >> 3) * 16 + row) * Wc + (tile & 7) * 16 + col;
    out[(b * 3 + 0) * HWc + p] = r  * inv;
    out[(b * 3 + 1) * HWc + p] = gg * inv;
    out[(b * 3 + 2) * HWc + p] = bb * inv;
}

// ---------------------------------------------------------------------------
extern "C" void kernel_launch(void* const* d_in, const int* in_sizes, int n_in,
                              void* d_out, int out_size) {
    const float* pos = (const float*)d_in[0];
    const float* col = (const float*)d_in[1];
    const float* opa = (const float*)d_in[2];
    const float* scl = (const float*)d_in[3];
    const float* qv  = (const float*)d_in[4];
    const float* tv  = (const float*)d_in[5];
    const float* fx  = (const float*)d_in[6];
    const float* fy  = (const float*)d_in[7];
    const float* cx  = (const float*)d_in[8];
    const float* cy  = (const float*)d_in[9];

    k_colop<<<Nc / 256, 256>>>(col, opa);
    k_params<<<(Bc * Nc) / 256, 256>>>(pos, opa, scl, qv, tv, fx, fy, cx, cy);
    k_scan<<<1, 256>>>();
    k_scatter<<<(Bc * Nc) / 256, 256>>>();
    k_splat<<<MAXITEMS, NTHR>>>();
    k_finalize<<<NBT, 256>>>((float*)d_out);
}

// round 12
// speedup vs baseline: 1.1306x; 1.1306x over previous
#include <cuda_runtime.h>

// Problem constants (fixed by reference_code)
#define Bc 2
#define Nc 65536
#define Hc 128
#define Wc 128
#define HWc 16384
#define TDIMX 16
#define TDIMY 16
#define NTILE 64               // tiles per camera (8x8)
#define NBT (Bc * NTILE)       // 128 (camera, tile) pairs
#define NCHUNK 256             // 256-gaussian chunks per camera
#define SEG 256                // list entries per splat work item
#define KC 32                  // staged chunk in splat
#define NTHR 128
// cutoff: op*exp(a*d^2) <= e^-14 ~ 8.3e-7; validated rel_err ~9.3e-7 (R7-R11)
#define CULL_LN (-14.0f)
#define LISTCAP (Bc * Nc * 9 + 64)   // every gaussian covers <= 9 tiles (2r < 32)
#define MAXITEMS 4800                // >= LISTCAP/SEG + NBT

// Scratch (static __device__ arrays — no allocation at runtime)
__device__ float4 g_params[Bc * Nc];            // proj_x, proj_y, a=-0.5/var, opacity
__device__ float4 g_colop[Nc];                  // (op*cr, op*cg, op*cb, op)
__device__ unsigned long long g_mask[Bc * Nc];  // 64-bit tile cover mask
__device__ unsigned int g_cnt[NBT * NCHUNK];    // per (b,tile,chunk) counts
__device__ unsigned int g_off[NBT * NCHUNK];    // exclusive prefix within (b,tile)
__device__ int g_tilebase[NBT + 1];             // list base per (b,tile)
__device__ int g_itembase[NBT + 1];             // item base per (b,tile)
__device__ int g_nitems;
__device__ unsigned int g_items[MAXITEMS];      // b<<24 | tile<<16 | seg
__device__ unsigned short g_list[LISTCAP];      // gaussian index within camera
__device__ float g_part[(size_t)MAXITEMS * 1024]; // per-item partials [4ch][256px]

// ---------------------------------------------------------------------------
// Kernel 1: projection params + colop fold + tile mask + per-chunk counts.
//   grid = 512 blocks (b = blk>>8, chunk c = blk&255), 256 threads.
// ---------------------------------------------------------------------------
__global__ void __launch_bounds__(256) k_params(
        const float* __restrict__ pos,
        const float* __restrict__ colors,
        const float* __restrict__ opa,
        const float* __restrict__ scl,
        const float* __restrict__ qv,
        const float* __restrict__ tv,
        const float* __restrict__ fx_,
        const float* __restrict__ fy_,
        const float* __restrict__ cx_,
        const float* __restrict__ cy_) {
    __shared__ unsigned int scnt[NTILE];

    const int t = threadIdx.x;
    const int b = blockIdx.x >> 8;
    const int c = blockIdx.x & 255;
    const int n = c * 256 + t;
    const int idx = b * Nc + n;

    if (t < NTILE) scnt[t] = 0u;
    __syncthreads();

    float qw = qv[b * 4 + 0], qx = qv[b * 4 + 1], qy = qv[b * 4 + 2], qz = qv[b * 4 + 3];
    float inv = rsqrtf(qw * qw + qx * qx + qy * qy + qz * qz);
    qw *= inv; qx *= inv; qy *= inv; qz *= inv;

    float R00 = 1.f - 2.f * (qy * qy + qz * qz);
    float R01 = 2.f * (qx * qy - qz * qw);
    float R02 = 2.f * (qx * qz + qy * qw);
    float R10 = 2.f * (qx * qy + qz * qw);
    float R11 = 1.f - 2.f * (qx * qx + qz * qz);
    float R12 = 2.f * (qy * qz - qx * qw);
    float R20 = 2.f * (qx * qz - qy * qw);
    float R21 = 2.f * (qy * qz + qx * qw);
    float R22 = 1.f - 2.f * (qx * qx + qy * qy);

    float px = pos[3 * n], py = pos[3 * n + 1], pz = pos[3 * n + 2];
    float cxm = R00 * px + R01 * py + R02 * pz + tv[b * 3 + 0];
    float cym = R10 * px + R11 * py + R12 * pz + tv[b * 3 + 1];
    float czm = R20 * px + R21 * py + R22 * pz + tv[b * 3 + 2];

    float projx = cxm / czm * fx_[0] + cx_[0];
    float projy = cym / czm * fy_[0] + cy_[0];
    float op = opa[n];
    float s = scl[n];
    float a = -0.5f / (s * s);

    g_params[idx] = make_float4(projx, projy, a, op);

    if (b == 0) {
        g_colop[n] = make_float4(op * colors[3 * n], op * colors[3 * n + 1],
                                 op * colors[3 * n + 2], op);
    }

    // tile cover mask (exact clamped-corner test, NaN-safe: NaN>=c is false)
    unsigned long long mask = 0ull;
    float r = sqrtf(CULL_LN / a);              // sqrt(28*var)
    int txlo = (int)fmaxf(0.f, fminf(7.f, floorf((projx - r) * 0.0625f)));
    int txhi = (int)fmaxf(0.f, fminf(7.f, floorf((projx + r) * 0.0625f)));
    int tylo = (int)fmaxf(0.f, fminf(7.f, floorf((projy - r) * 0.0625f)));
    int tyhi = (int)fmaxf(0.f, fminf(7.f, floorf((projy + r) * 0.0625f)));
    for (int ty = tylo; ty <= tyhi; ty++) {
        float ylo = (float)(ty * 16), yhi = ylo + 15.f;
        float ey = fmaxf(fmaxf(ylo - projy, projy - yhi), 0.f);
        for (int tx = txlo; tx <= txhi; tx++) {
            float xlo = (float)(tx * 16), xhi = xlo + 15.f;
            float ex = fmaxf(fmaxf(xlo - projx, projx - xhi), 0.f);
            if (a * (ex * ex + ey * ey) >= CULL_LN)
                mask |= 1ull << (ty * 8 + tx);
        }
    }
    g_mask[idx] = mask;

    // per-tile counts: <=9 smem atomics per thread (order-independent => exact)
    unsigned long long mm = mask;
    while (mm) {
        int tl = __ffsll((long long)mm) - 1;
        mm &= mm - 1;
        atomicAdd(&scnt[tl], 1u);
    }
    __syncthreads();
    if (t < NTILE) g_cnt[(b * NTILE + t) * NCHUNK + c] = scnt[t];
}

// ---------------------------------------------------------------------------
// Kernel 2: scan — per-(b,tile) chunk prefix (MLP=16 batched), tile bases,
//   item table. Single block, 256 threads.
// ---------------------------------------------------------------------------
__global__ void __launch_bounds__(256) k_scan() {
    __shared__ int slen[NBT];
    __shared__ int stb[NBT + 1];
    __shared__ int sib[NBT + 1];
    const int t = threadIdx.x;

    if (t < NBT) {
        unsigned run = 0;
        const int base = t * NCHUNK;
        for (int c0 = 0; c0 < NCHUNK; c0 += 16) {
            unsigned v[16];
#pragma unroll
            for (int i = 0; i < 16; i++) v[i] = g_cnt[base + c0 + i];  // MLP=16
#pragma unroll
            for (int i = 0; i < 16; i++) { g_off[base + c0 + i] = run; run += v[i]; }
        }
        slen[t] = (int)run;
    }
    __syncthreads();
    if (t == 0) {
        int tb = 0, ib = 0;
        for (int i = 0; i < NBT; i++) {
            stb[i] = tb; sib[i] = ib;
            tb += slen[i];
            ib += (slen[i] + SEG - 1) / SEG;
        }
        stb[NBT] = tb; sib[NBT] = ib;
        g_nitems = ib;
    }
    __syncthreads();
    if (t <= NBT) { g_tilebase[t] = stb[t]; g_itembase[t] = sib[t]; }
    if (t < NBT) {
        int ns = (slen[t] + SEG - 1) / SEG;
        unsigned hdr = ((unsigned)(t >> 6) << 24) | ((unsigned)(t & 63) << 16);
        for (int s = 0; s < ns; s++)
            g_items[sib[t] + s] = hdr | (unsigned)s;
    }
}

// ---------------------------------------------------------------------------
// Kernel 3: scatter gaussian indices into per-tile lists (index-ordered,
//   deterministic). Block-union skip avoids ballots on uncovered tiles.
//   grid = 512 blocks (b, chunk), 256 threads.
// ---------------------------------------------------------------------------
__global__ void __launch_bounds__(256) k_scatter() {
    __shared__ unsigned int bals[8][NTILE];
    __shared__ unsigned int uni_lo, uni_hi;

    const int t = threadIdx.x;
    const int b = blockIdx.x >> 8;
    const int c = blockIdx.x & 255;
    const int n = c * 256 + t;
    const unsigned long long mask = g_mask[b * Nc + n];
    const int wid = t >> 5, lane = t & 31;

    if (t == 0) { uni_lo = 0u; uni_hi = 0u; }
    __syncthreads();

    unsigned wlo = __reduce_or_sync(0xffffffffu, (unsigned)mask);
    unsigned whi = __reduce_or_sync(0xffffffffu, (unsigned)(mask >> 32));
    if (lane == 0) { atomicOr(&uni_lo, wlo); atomicOr(&uni_hi, whi); }
    __syncthreads();
    const unsigned long long uni =
        ((unsigned long long)uni_hi << 32) | (unsigned long long)uni_lo;

    for (int tl = 0; tl < NTILE; tl++) {
        if (!((uni >> tl) & 1ull)) continue;   // block-uniform skip
        unsigned bal = __ballot_sync(0xffffffffu, (mask >> tl) & 1ull);
        if (lane == 0) bals[wid][tl] = bal;
    }
    __syncthreads();

    unsigned long long mm = mask;
    while (mm) {
        int tl = __ffsll((long long)mm) - 1;
        mm &= mm - 1;
        int rank = 0;
#pragma unroll
        for (int w = 0; w < 8; w++) {
            unsigned bb = bals[w][tl];
            if (w < wid) rank += __popc(bb);
            else if (w == wid) rank += __popc(bb & ((1u << lane) - 1u));
        }
        int bt = b * NTILE + tl;
        int pos = g_tilebase[bt] + (int)g_off[bt * NCHUNK + c] + rank;
        g_list[pos] = (unsigned short)n;
    }
}

// ---------------------------------------------------------------------------
// Kernel 4: splat — one 256-entry list segment per block (perfect balance).
//   grid = MAXITEMS blocks (early exit past g_nitems), 128 threads.
//   Merged u/d staging: one lst read + one prm load + two exps per slot.
//   Inner: LDS.64 + LDS.128 + 8 FFMA per gaussian per thread.
// ---------------------------------------------------------------------------
__global__ void __launch_bounds__(NTHR) k_splat() {
    __shared__ float  us[KC][TDIMX];
    __shared__ float4 ds[KC][TDIMY];
    __shared__ unsigned short lst[SEG];

    const int item = blockIdx.x;
    if (item >= g_nitems) return;
    const unsigned rec = g_items[item];
    const int b = rec >> 24, tile = (rec >> 16) & 0xff, seg = rec & 0xffff;
    const int bt = b * NTILE + tile;
    const int base = g_tilebase[bt];
    const int len = g_tilebase[bt + 1] - base;
    const int start = seg * SEG;
    const int m = min(SEG, len - start);
    const int t = threadIdx.x;

    // preload list slice (scalar u16 loads — base may be odd)
    if (t < m)        lst[t] = g_list[base + start + t];
    if (t + NTHR < m) lst[t + NTHR] = g_list[base + start + t + NTHR];

    const float4* __restrict__ prm = &g_params[b * Nc];
    const int x0 = (tile & 7) * TDIMX, y0 = (tile >> 3) * TDIMY;
    const int tx = t & 7, tyy = t >> 3;     // 2x * 1y micro-tile
    const int xu = t & 15, ku0 = t >> 4;    // staging: 4 slots (k = ku0 + 8i)

    float acc[2][4];
#pragma unroll
    for (int xi = 0; xi < 2; xi++)
#pragma unroll
        for (int ch = 0; ch < 4; ch++) acc[xi][ch] = 0.f;

    __syncthreads();

    for (int kb = 0; kb < m; kb += KC) {
        // ---- merged staging: u and d for the same k from one prm load
#pragma unroll
        for (int i = 0; i < 4; i++) {
            int k = ku0 + i * 8;
            int kk = kb + k;
            float u = 0.f;
            float4 dval = make_float4(0.f, 0.f, 0.f, 0.f);
            if (kk < m) {
                int n = (int)lst[kk];
                float4 pr = prm[n];
                float4 co = g_colop[n];
                float dx = (float)(x0 + xu) - pr.x;
                float dy = (float)(y0 + xu) - pr.y;
                u = __expf(pr.z * dx * dx);
                float e = __expf(pr.z * dy * dy);
                dval = make_float4(co.x * e, co.y * e, co.z * e, co.w * e);
            }
            us[k][xu] = u;
            ds[k][xu] = dval;
        }
        __syncthreads();

        // ---- inner: 8 FFMA + LDS.64 + LDS.128 per k
#pragma unroll 16
        for (int k = 0; k < KC; k++) {
            float2 u2 = *reinterpret_cast<const float2*>(&us[k][tx * 2]);
            float4 d  = ds[k][tyy];
            acc[0][0] += u2.x * d.x;
            acc[0][1] += u2.x * d.y;
            acc[0][2] += u2.x * d.z;
            acc[0][3] += u2.x * d.w;
            acc[1][0] += u2.y * d.x;
            acc[1][1] += u2.y * d.y;
            acc[1][2] += u2.y * d.z;
            acc[1][3] += u2.y * d.w;
        }
        __syncthreads();
    }

    // ---- write per-item partial [4ch][256px]
    float* pb = &g_part[(size_t)item * 1024];
    const int p = tyy * 16 + tx * 2;
#pragma unroll
    for (int ch = 0; ch < 4; ch++)
        *reinterpret_cast<float2*>(&pb[ch * 256 + p]) =
            make_float2(acc[0][ch], acc[1][ch]);
}

// ---------------------------------------------------------------------------
// Kernel 5: finalize — per-(b,tile) block sums its segments, divides, writes.
// ---------------------------------------------------------------------------
__global__ void __launch_bounds__(256) k_finalize(float* __restrict__ out) {
    const int bt = blockIdx.x;
    const int b = bt >> 6, tile = bt & 63;
    const int t = threadIdx.x;
    const int itb = g_itembase[bt];
    const int ns = g_itembase[bt + 1] - itb;

    float r = 0.f, gg = 0.f, bb = 0.f;
    float d = 32.0f * 1e-8f;   // n_chunks(=32 of 2048) * EPS from reference scan
    for (int s = 0; s < ns; s++) {
        const float* pb = &g_part[(size_t)(itb + s) * 1024];
        r  += pb[t];
        gg += pb[256 + t];
        bb += pb[512 + t];
        d  += pb[768 + t];
    }
    float inv = 1.0f / fmaxf(d, 1e-8f);
    const int col = t & 15, row = t >> 4;
    const int p = ((tile >> 3) * 16 + row) * Wc + (tile & 7) * 16 + col;
    out[(b * 3 + 0) * HWc + p] = r  * inv;
    out[(b * 3 + 1) * HWc + p] = gg * inv;
    out[(b * 3 + 2) * HWc + p] = bb * inv;
}

// ---------------------------------------------------------------------------
extern "C" void kernel_launch(void* const* d_in, const int* in_sizes, int n_in,
                              void* d_out, int out_size) {
    const float* pos = (const float*)d_in[0];
    const float* col = (const float*)d_in[1];
    const float* opa = (const float*)d_in[2];
    const float* scl = (const float*)d_in[3];
    const float* qv  = (const float*)d_in[4];
    const float* tv  = (const float*)d_in[5];
    const float* fx  = (const float*)d_in[6];
    const float* fy  = (const float*)d_in[7];
    const float* cx  = (const float*)d_in[8];
    const float* cy  = (const float*)d_in[9];

    k_params<<<(Bc * Nc) / 256, 256>>>(pos, col, opa, scl, qv, tv, fx, fy, cx, cy);
    k_scan<<<1, 256>>>();
    k_scatter<<<(Bc * Nc) / 256, 256>>>();
    k_splat<<<MAXITEMS, NTHR>>>();
    k_finalize<<<NBT, 256>>>((float*)d_out);
}

// round 13
// speedup vs baseline: 1.2099x; 1.0702x over previous
#include <cuda_runtime.h>

// Problem constants (fixed by reference_code)
#define Bc 2
#define Nc 65536
#define Hc 128
#define Wc 128
#define HWc 16384
#define TDIMX 16
#define TDIMY 16
#define NTILE 64               // tiles per camera (8x8)
#define NBT (Bc * NTILE)       // 128 (camera, tile) pairs
#define NCHUNK 256             // 256-gaussian chunks per camera
#define SEG 512                // list entries per splat work item
#define KC 32                  // staged chunk in splat
#define NTHR 128
// cutoff: op*exp(a*d^2) <= e^-14 ~ 8.3e-7; validated rel_err ~9.3e-7 (R7-R12)
#define CULL_LN (-14.0f)
#define LISTCAP (Bc * Nc * 9 + 64)   // every gaussian covers <= 9 tiles (2r < 32)
#define MAXITEMS 2560                // >= LISTCAP/SEG + NBT

// Scratch (static __device__ arrays — no allocation at runtime)
__device__ float4 g_params[Bc * Nc];            // proj_x, proj_y, a=-0.5/var, opacity
__device__ float4 g_colop[Nc];                  // (op*cr, op*cg, op*cb, op)
__device__ unsigned long long g_mask[Bc * Nc];  // 64-bit tile cover mask
__device__ unsigned int g_cnt[NBT * NCHUNK];    // per (b,tile,chunk) counts
__device__ unsigned int g_off[NBT * NCHUNK];    // exclusive prefix within (b,tile)
__device__ int g_tilebase[NBT + 1];             // list base per (b,tile)
__device__ int g_itembase[NBT + 1];             // item base per (b,tile)
__device__ int g_nitems;
__device__ unsigned int g_items[MAXITEMS];      // b<<24 | tile<<16 | seg
__device__ unsigned short g_list[LISTCAP];      // gaussian index within camera
__device__ float g_part[(size_t)MAXITEMS * 1024]; // per-item partials [4ch][256px]

// ---------------------------------------------------------------------------
// Kernel 1: projection params + colop fold + tile mask + per-chunk counts.
//   grid = 512 blocks (b = blk>>8, chunk c = blk&255), 256 threads.
// ---------------------------------------------------------------------------
__global__ void __launch_bounds__(256) k_params(
        const float* __restrict__ pos,
        const float* __restrict__ colors,
        const float* __restrict__ opa,
        const float* __restrict__ scl,
        const float* __restrict__ qv,
        const float* __restrict__ tv,
        const float* __restrict__ fx_,
        const float* __restrict__ fy_,
        const float* __restrict__ cx_,
        const float* __restrict__ cy_) {
    __shared__ unsigned int scnt[NTILE];

    const int t = threadIdx.x;
    const int b = blockIdx.x >> 8;
    const int c = blockIdx.x & 255;
    const int n = c * 256 + t;
    const int idx = b * Nc + n;

    if (t < NTILE) scnt[t] = 0u;
    __syncthreads();

    float qw = qv[b * 4 + 0], qx = qv[b * 4 + 1], qy = qv[b * 4 + 2], qz = qv[b * 4 + 3];
    float inv = rsqrtf(qw * qw + qx * qx + qy * qy + qz * qz);
    qw *= inv; qx *= inv; qy *= inv; qz *= inv;

    float R00 = 1.f - 2.f * (qy * qy + qz * qz);
    float R01 = 2.f * (qx * qy - qz * qw);
    float R02 = 2.f * (qx * qz + qy * qw);
    float R10 = 2.f * (qx * qy + qz * qw);
    float R11 = 1.f - 2.f * (qx * qx + qz * qz);
    float R12 = 2.f * (qy * qz - qx * qw);
    float R20 = 2.f * (qx * qz - qy * qw);
    float R21 = 2.f * (qy * qz + qx * qw);
    float R22 = 1.f - 2.f * (qx * qx + qy * qy);

    float px = pos[3 * n], py = pos[3 * n + 1], pz = pos[3 * n + 2];
    float cxm = R00 * px + R01 * py + R02 * pz + tv[b * 3 + 0];
    float cym = R10 * px + R11 * py + R12 * pz + tv[b * 3 + 1];
    float czm = R20 * px + R21 * py + R22 * pz + tv[b * 3 + 2];

    float projx = cxm / czm * fx_[0] + cx_[0];
    float projy = cym / czm * fy_[0] + cy_[0];
    float op = opa[n];
    float s = scl[n];
    float a = -0.5f / (s * s);

    g_params[idx] = make_float4(projx, projy, a, op);

    if (b == 0) {
        g_colop[n] = make_float4(op * colors[3 * n], op * colors[3 * n + 1],
                                 op * colors[3 * n + 2], op);
    }

    // tile cover mask (exact clamped-corner test, NaN-safe: NaN>=c is false)
    unsigned long long mask = 0ull;
    float r = sqrtf(CULL_LN / a);              // sqrt(28*var)
    int txlo = (int)fmaxf(0.f, fminf(7.f, floorf((projx - r) * 0.0625f)));
    int txhi = (int)fmaxf(0.f, fminf(7.f, floorf((projx + r) * 0.0625f)));
    int tylo = (int)fmaxf(0.f, fminf(7.f, floorf((projy - r) * 0.0625f)));
    int tyhi = (int)fmaxf(0.f, fminf(7.f, floorf((projy + r) * 0.0625f)));
    for (int ty = tylo; ty <= tyhi; ty++) {
        float ylo = (float)(ty * 16), yhi = ylo + 15.f;
        float ey = fmaxf(fmaxf(ylo - projy, projy - yhi), 0.f);
        for (int tx = txlo; tx <= txhi; tx++) {
            float xlo = (float)(tx * 16), xhi = xlo + 15.f;
            float ex = fmaxf(fmaxf(xlo - projx, projx - xhi), 0.f);
            if (a * (ex * ex + ey * ey) >= CULL_LN)
                mask |= 1ull << (ty * 8 + tx);
        }
    }
    g_mask[idx] = mask;

    // per-tile counts: <=9 smem atomics per thread (order-independent => exact)
    unsigned long long mm = mask;
    while (mm) {
        int tl = __ffsll((long long)mm) - 1;
        mm &= mm - 1;
        atomicAdd(&scnt[tl], 1u);
    }
    __syncthreads();
    if (t < NTILE) g_cnt[(b * NTILE + t) * NCHUNK + c] = scnt[t];
}

// ---------------------------------------------------------------------------
// Kernel 2: scan — per-(b,tile) chunk prefix (MLP=16 batched), tile bases,
//   item table. Single block, 256 threads.
// ---------------------------------------------------------------------------
__global__ void __launch_bounds__(256) k_scan() {
    __shared__ int slen[NBT];
    __shared__ int stb[NBT + 1];
    __shared__ int sib[NBT + 1];
    const int t = threadIdx.x;

    if (t < NBT) {
        unsigned run = 0;
        const int base = t * NCHUNK;
        for (int c0 = 0; c0 < NCHUNK; c0 += 16) {
            unsigned v[16];
#pragma unroll
            for (int i = 0; i < 16; i++) v[i] = g_cnt[base + c0 + i];  // MLP=16
#pragma unroll
            for (int i = 0; i < 16; i++) { g_off[base + c0 + i] = run; run += v[i]; }
        }
        slen[t] = (int)run;
    }
    __syncthreads();
    if (t == 0) {
        int tb = 0, ib = 0;
        for (int i = 0; i < NBT; i++) {
            stb[i] = tb; sib[i] = ib;
            tb += slen[i];
            ib += (slen[i] + SEG - 1) / SEG;
        }
        stb[NBT] = tb; sib[NBT] = ib;
        g_nitems = ib;
    }
    __syncthreads();
    if (t <= NBT) { g_tilebase[t] = stb[t]; g_itembase[t] = sib[t]; }
    if (t < NBT) {
        int ns = (slen[t] + SEG - 1) / SEG;
        unsigned hdr = ((unsigned)(t >> 6) << 24) | ((unsigned)(t & 63) << 16);
        for (int s = 0; s < ns; s++)
            g_items[sib[t] + s] = hdr | (unsigned)s;
    }
}

// ---------------------------------------------------------------------------
// Kernel 3: scatter gaussian indices into per-tile lists (index-ordered,
//   deterministic). grid = 512 blocks (b, chunk), 256 threads.
// ---------------------------------------------------------------------------
__global__ void __launch_bounds__(256) k_scatter() {
    __shared__ unsigned int bals[8][NTILE];
    __shared__ unsigned int uni_lo, uni_hi;

    const int t = threadIdx.x;
    const int b = blockIdx.x >> 8;
    const int c = blockIdx.x & 255;
    const int n = c * 256 + t;
    const unsigned long long mask = g_mask[b * Nc + n];
    const int wid = t >> 5, lane = t & 31;

    if (t == 0) { uni_lo = 0u; uni_hi = 0u; }
    __syncthreads();

    unsigned wlo = __reduce_or_sync(0xffffffffu, (unsigned)mask);
    unsigned whi = __reduce_or_sync(0xffffffffu, (unsigned)(mask >> 32));
    if (lane == 0) { atomicOr(&uni_lo, wlo); atomicOr(&uni_hi, whi); }
    __syncthreads();
    const unsigned long long uni =
        ((unsigned long long)uni_hi << 32) | (unsigned long long)uni_lo;

    for (int tl = 0; tl < NTILE; tl++) {
        if (!((uni >> tl) & 1ull)) continue;   // block-uniform skip
        unsigned bal = __ballot_sync(0xffffffffu, (mask >> tl) & 1ull);
        if (lane == 0) bals[wid][tl] = bal;
    }
    __syncthreads();

    unsigned long long mm = mask;
    while (mm) {
        int tl = __ffsll((long long)mm) - 1;
        mm &= mm - 1;
        int rank = 0;
#pragma unroll
        for (int w = 0; w < 8; w++) {
            unsigned bb = bals[w][tl];
            if (w < wid) rank += __popc(bb);
            else if (w == wid) rank += __popc(bb & ((1u << lane) - 1u));
        }
        int bt = b * NTILE + tl;
        int pos = g_tilebase[bt] + (int)g_off[bt * NCHUNK + c] + rank;
        g_list[pos] = (unsigned short)n;
    }
}

// ---------------------------------------------------------------------------
// Kernel 4: splat — one 512-entry list segment per block, software-pipelined:
//   per chunk: STS-stage from regs -> prefetch next chunk's LDGs -> BAR ->
//   inner FFMA loop. One bar per chunk; staging latency hidden under compute.
//   grid = MAXITEMS blocks (early exit past g_nitems), 128 threads.
// ---------------------------------------------------------------------------
__global__ void __launch_bounds__(NTHR) k_splat() {
    __shared__ float  us[2][KC][TDIMX];     // 4 KB
    __shared__ float4 ds[2][KC][TDIMY];     // 16 KB
    __shared__ unsigned short lst[SEG];     // 1 KB

    const int item = blockIdx.x;
    if (item >= g_nitems) return;
    const unsigned rec = g_items[item];
    const int b = rec >> 24, tile = (rec >> 16) & 0xff, seg = rec & 0xffff;
    const int bt = b * NTILE + tile;
    const int base = g_tilebase[bt];
    const int len = g_tilebase[bt + 1] - base;
    const int start = seg * SEG;
    const int m = min(SEG, len - start);
    const int t = threadIdx.x;

    // preload list slice (scalar u16 loads — base may be odd)
#pragma unroll
    for (int i = 0; i < SEG / NTHR; i++)
        if (t + i * NTHR < m) lst[t + i * NTHR] = g_list[base + start + t + i * NTHR];

    const float4* __restrict__ prm = &g_params[b * Nc];
    const int x0 = (tile & 7) * TDIMX, y0 = (tile >> 3) * TDIMY;
    const int tx = t & 7, tyy = t >> 3;     // 2x * 1y micro-tile
    const int xu = t & 15, ku0 = t >> 4;    // staging: 4 slots (k = ku0 + 8i)

    float acc[2][4];
#pragma unroll
    for (int xi = 0; xi < 2; xi++)
#pragma unroll
        for (int ch = 0; ch < 4; ch++) acc[xi][ch] = 0.f;

    __syncthreads();   // lst visible

    // prefetch chunk 0 into registers
    float4 pr[4], co[4];
#pragma unroll
    for (int i = 0; i < 4; i++) {
        int kk = ku0 + i * 8;
        if (kk < m) {
            int n = (int)lst[kk];
            pr[i] = prm[n];
            co[i] = g_colop[n];
        } else {
            pr[i] = make_float4(0.f, 0.f, 0.f, 0.f);   // a=0 -> u=1, d=0
            co[i] = make_float4(0.f, 0.f, 0.f, 0.f);
        }
    }

    const int nch = (m + KC - 1) / KC;
    for (int c = 0; c < nch; c++) {
        const int buf = c & 1;

        // ---- stage chunk c from registers (exps + STS)
#pragma unroll
        for (int i = 0; i < 4; i++) {
            int k = ku0 + i * 8;
            float dx = (float)(x0 + xu) - pr[i].x;
            float dy = (float)(y0 + xu) - pr[i].y;
            float u  = __expf(pr[i].z * dx * dx);
            float e  = __expf(pr[i].z * dy * dy);
            us[buf][k][xu] = u;
            ds[buf][k][xu] = make_float4(co[i].x * e, co[i].y * e,
                                         co[i].z * e, co[i].w * e);
        }

        // ---- prefetch chunk c+1 (LDGs overlap with inner loop below)
        const int kb2 = (c + 1) * KC;
#pragma unroll
        for (int i = 0; i < 4; i++) {
            int kk = kb2 + ku0 + i * 8;
            if (kk < m) {
                int n = (int)lst[kk];
                pr[i] = prm[n];
                co[i] = g_colop[n];
            } else {
                pr[i] = make_float4(0.f, 0.f, 0.f, 0.f);
                co[i] = make_float4(0.f, 0.f, 0.f, 0.f);
            }
        }

        __syncthreads();

        // ---- inner: 8 FFMA + LDS.64 + LDS.128 per k per thread
#pragma unroll 16
        for (int k = 0; k < KC; k++) {
            float2 u2 = *reinterpret_cast<const float2*>(&us[buf][k][tx * 2]);
            float4 d  = ds[buf][k][tyy];
            acc[0][0] += u2.x * d.x;
            acc[0][1] += u2.x * d.y;
            acc[0][2] += u2.x * d.z;
            acc[0][3] += u2.x * d.w;
            acc[1][0] += u2.y * d.x;
            acc[1][1] += u2.y * d.y;
            acc[1][2] += u2.y * d.z;
            acc[1][3] += u2.y * d.w;
        }
    }

    // ---- write per-item partial [4ch][256px]
    float* pb = &g_part[(size_t)item * 1024];
    const int p = tyy * 16 + tx * 2;
#pragma unroll
    for (int ch = 0; ch < 4; ch++)
        *reinterpret_cast<float2*>(&pb[ch * 256 + p]) =
            make_float2(acc[0][ch], acc[1][ch]);
}

// ---------------------------------------------------------------------------
// Kernel 5: finalize — per-(b,tile) block sums its segments, divides, writes.
// ---------------------------------------------------------------------------
__global__ void __launch_bounds__(256) k_finalize(float* __restrict__ out) {
    const int bt = blockIdx.x;
    const int b = bt >> 6, tile = bt & 63;
    const int t = threadIdx.x;
    const int itb = g_itembase[bt];
    const int ns = g_itembase[bt + 1] - itb;

    float r = 0.f, gg = 0.f, bb = 0.f;
    float d = 32.0f * 1e-8f;   // n_chunks(=32 of 2048) * EPS from reference scan
    for (int s = 0; s < ns; s++) {
        const float* pb = &g_part[(size_t)(itb + s) * 1024];
        r  += pb[t];
        gg += pb[256 + t];
        bb += pb[512 + t];
        d  += pb[768 + t];
    }
    float inv = 1.0f / fmaxf(d, 1e-8f);
    const int col = t & 15, row = t >> 4;
    const int p = ((tile >> 3) * 16 + row) * Wc + (tile & 7) * 16 + col;
    out[(b * 3 + 0) * HWc + p] = r  * inv;
    out[(b * 3 + 1) * HWc + p] = gg * inv;
    out[(b * 3 + 2) * HWc + p] = bb * inv;
}

// ---------------------------------------------------------------------------
extern "C" void kernel_launch(void* const* d_in, const int* in_sizes, int n_in,
                              void* d_out, int out_size) {
    const float* pos = (const float*)d_in[0];
    const float* col = (const float*)d_in[1];
    const float* opa = (const float*)d_in[2];
    const float* scl = (const float*)d_in[3];
    const float* qv  = (const float*)d_in[4];
    const float* tv  = (const float*)d_in[5];
    const float* fx  = (const float*)d_in[6];
    const float* fy  = (const float*)d_in[7];
    const float* cx  = (const float*)d_in[8];
    const float* cy  = (const float*)d_in[9];

    k_params<<<(Bc * Nc) / 256, 256>>>(pos, col, opa, scl, qv, tv, fx, fy, cx, cy);
    k_scan<<<1, 256>>>();
    k_scatter<<<(Bc * Nc) / 256, 256>>>();
    k_splat<<<MAXITEMS, NTHR>>>();
    k_finalize<<<NBT, 256>>>((float*)d_out);
}